// round 1
// baseline (speedup 1.0000x reference)
#include <cuda_runtime.h>
#include <cuda_bf16.h>
#include <mma.h>

using namespace nvcuda;

// Problem constants
#define NB    32
#define NC    128
#define NH    56
#define NW    56
#define HP    58                 // padded spatial
#define PIX   3136               // 56*56
#define MTOT  100352             // 32*3136
#define PAD_ELEMS (32*58*58*128) // 13,778,944

// Device scratch (allocation-free rule: __device__ globals)
__device__ __nv_bfloat16 g_qh[PAD_ELEMS];      // padded NHWC uint8-valued acts (high)
__device__ __nv_bfloat16 g_ql[PAD_ELEMS];      // padded NHWC uint4-valued acts (low)
__device__ __nv_bfloat16 g_wqh[9 * 128 * 128]; // [tap][ic][oc]
__device__ __nv_bfloat16 g_wql[9 * 128 * 128];
__device__ float g_sh[128];                    // s_w_high[oc] * act_scale_high
__device__ float g_sl[128];
__device__ unsigned char g_mask[32 * 128 * 49];

// ---------------------------------------------------------------------------
// 1) Pool mask: one warp per (b, c, 7x7 cell), mean of 8x8 block >= 0.05
// ---------------------------------------------------------------------------
__global__ void mask_kernel(const float* __restrict__ x) {
    int cell = blockIdx.x * 8 + (threadIdx.x >> 5);
    int lane = threadIdx.x & 31;
    int b   = cell / (128 * 49);
    int rem = cell - b * (128 * 49);
    int c   = rem / 49;
    int pc  = rem - c * 49;
    int bh  = pc / 7;
    int bw  = pc - bh * 7;
    const float* base = x + (((b * 128 + c) * 56 + bh * 8) * 56 + bw * 8);
    int r = lane >> 3, col = lane & 7;
    float s = base[r * 56 + col] + base[(r + 4) * 56 + col];
#pragma unroll
    for (int o = 16; o > 0; o >>= 1) s += __shfl_xor_sync(0xffffffffu, s, o);
    if (lane == 0) g_mask[cell] = (s * (1.0f / 64.0f)) >= 0.05f ? 1 : 0;
}

// ---------------------------------------------------------------------------
// 2) Zero the padded borders of g_qh / g_ql (interior is fully written below)
//    32 images * 228 border pixels * 128 channels
// ---------------------------------------------------------------------------
__global__ void border_kernel() {
    int idx = blockIdx.x * 256 + threadIdx.x;   // < 933888
    int c = idx & 127;
    int t = idx >> 7;                            // 0..7295
    int b = t / 228;
    int e = t - b * 228;
    int h, w;
    if (e < 58)       { h = 0;  w = e; }
    else if (e < 116) { h = 57; w = e - 58; }
    else { int r = e - 116; h = 1 + (r >> 1); w = (r & 1) ? 57 : 0; }
    long off = (((long)(b * 58 + h)) * 58 + w) * 128 + c;
    __nv_bfloat16 z = __float2bfloat16(0.0f);
    g_qh[off] = z;
    g_ql[off] = z;
}

// ---------------------------------------------------------------------------
// 3) Quantize acts, NCHW -> padded NHWC bf16 (integer-valued), via smem transpose
//    one block per (b, h) row
// ---------------------------------------------------------------------------
__global__ void quant_kernel(const float* __restrict__ x,
                             const float* __restrict__ p_sh,
                             const float* __restrict__ p_sl) {
    __shared__ float xs[128 * 57];
    __shared__ unsigned char ms[128 * 7];
    int blk = blockIdx.x;            // b*56 + h
    int b = blk / 56, h = blk - b * 56;
    int tid = threadIdx.x;
    for (int i = tid; i < 128 * 56; i += 256) {
        int c = i / 56, w = i - c * 56;
        xs[c * 57 + w] = x[(((b * 128 + c) * 56 + h)) * 56 + w];
    }
    for (int i = tid; i < 128 * 7; i += 256) {
        int c = i / 7, bw = i - c * 7;
        ms[i] = g_mask[(b * 128 + c) * 49 + (h >> 3) * 7 + bw];
    }
    __syncthreads();
    float sh = *p_sh, sl = *p_sl;
    long pixrow = (((long)(b * 58) + h + 1) * 58 + 1) * 128;  // elem offset of (h+1, w=1, c=0)
    unsigned int* outh = (unsigned int*)g_qh;
    unsigned int* outl = (unsigned int*)g_ql;
    for (int i = tid; i < 64 * 56; i += 256) {
        int w  = i >> 6;
        int c2 = i & 63;
        int c  = c2 * 2;
        int mb = w >> 3;
        bool m0 = ms[c * 7 + mb] != 0;
        bool m1 = ms[(c + 1) * 7 + mb] != 0;
        float v0 = xs[c * 57 + w], v1 = xs[(c + 1) * 57 + w];
        // exact IEEE division to match the reference's x/scale bitwise
        float q0h = m0 ? fminf(fmaxf(rintf(v0 / sh), 0.f), 255.f) : 0.f;
        float q1h = m1 ? fminf(fmaxf(rintf(v1 / sh), 0.f), 255.f) : 0.f;
        float q0l = m0 ? 0.f : fminf(fmaxf(rintf(v0 / sl), 0.f), 15.f);
        float q1l = m1 ? 0.f : fminf(fmaxf(rintf(v1 / sl), 0.f), 15.f);
        unsigned uh = (unsigned)__bfloat16_as_ushort(__float2bfloat16(q0h)) |
                      ((unsigned)__bfloat16_as_ushort(__float2bfloat16(q1h)) << 16);
        unsigned ul = (unsigned)__bfloat16_as_ushort(__float2bfloat16(q0l)) |
                      ((unsigned)__bfloat16_as_ushort(__float2bfloat16(q1l)) << 16);
        long widx = (pixrow + (long)w * 128 + c) >> 1;
        outh[widx] = uh;
        outl[widx] = ul;
    }
}

// ---------------------------------------------------------------------------
// 4) Weight quantization: one block per oc, per-oc max|w|/n, write [tap][ic][oc]
// ---------------------------------------------------------------------------
__global__ void wq_kernel(const float* __restrict__ w, const float* __restrict__ ascale, int high) {
    __shared__ float red[128];
    int oc = blockIdx.x;
    int ic = threadIdx.x;
    float n = high ? 127.0f : 7.0f;
    const float* wp = w + ((long)oc * 128 + ic) * 9;
    float m = 0.f;
#pragma unroll
    for (int t = 0; t < 9; t++) m = fmaxf(m, fabsf(wp[t]));
    red[ic] = m;
    __syncthreads();
    for (int s = 64; s > 0; s >>= 1) {
        if (ic < s) red[ic] = fmaxf(red[ic], red[ic + s]);
        __syncthreads();
    }
    float s_w = red[0] / n;
    __nv_bfloat16* dst = high ? g_wqh : g_wql;
#pragma unroll
    for (int t = 0; t < 9; t++) {
        float q = fminf(fmaxf(rintf(wp[t] / s_w), -n), n);
        dst[(t * 128 + ic) * 128 + oc] = __float2bfloat16(q);
    }
    if (ic == 0) (high ? g_sh : g_sl)[oc] = s_w * (*ascale);
}

// ---------------------------------------------------------------------------
// 5) Implicit-GEMM dual conv: 128 pixels x 128 oc per CTA, K = 9 taps x 128 ic.
//    bf16 wmma (exact integer math), fp32 accum, scale-sum epilogue.
// ---------------------------------------------------------------------------
__global__ void __launch_bounds__(256, 1) conv_kernel(float* __restrict__ out) {
    extern __shared__ char smem[];
    __nv_bfloat16* Ah = (__nv_bfloat16*)smem;     // [128 pix][128 ic]
    __nv_bfloat16* Al = Ah + 16384;
    __nv_bfloat16* Wh = Al + 16384;               // [128 ic][128 oc]
    __nv_bfloat16* Wl = Wh + 16384;
    float* Oh = (float*)smem;                     // epilogue reuse: [oc][pix]
    float* Ol = Oh + 16384;

    int tid = threadIdx.x;
    int p = tid >> 1, half = tid & 1;
    int g = blockIdx.x * 128 + p;
    int b = g / 3136;
    int r = g - b * 3136;
    int h = r / 56;
    int w = r - h * 56;
    long abase = (((long)(b * 58 + h)) * 58 + w) * 128;  // padded (h+kh, w+kw) base for kh=kw=0

    int warp = tid >> 5;
    int m0 = (warp >> 1) * 32;   // 4 warps along M
    int n0 = (warp & 1) * 64;    // 2 warps along N

    wmma::fragment<wmma::accumulator, 16, 16, 16, float> accH[2][4], accL[2][4];
#pragma unroll
    for (int i = 0; i < 2; i++)
#pragma unroll
        for (int j = 0; j < 4; j++) {
            wmma::fill_fragment(accH[i][j], 0.0f);
            wmma::fill_fragment(accL[i][j], 0.0f);
        }

#pragma unroll 1
    for (int t = 0; t < 9; t++) {
        __syncthreads();
        int kh = t / 3, kw = t - kh * 3;
        long toff = abase + (kh * 58 + kw) * 128;
        const uint4* sH = (const uint4*)(g_qh + toff) + half * 8;
        const uint4* sL = (const uint4*)(g_ql + toff) + half * 8;
        uint4* dH = (uint4*)(Ah + p * 128) + half * 8;
        uint4* dL = (uint4*)(Al + p * 128) + half * 8;
#pragma unroll
        for (int j = 0; j < 8; j++) { dH[j] = sH[j]; dL[j] = sL[j]; }
        const uint4* wsH = (const uint4*)(g_wqh + t * 16384);
        const uint4* wsL = (const uint4*)(g_wql + t * 16384);
        uint4* wdH = (uint4*)Wh;
        uint4* wdL = (uint4*)Wl;
#pragma unroll
        for (int j = 0; j < 8; j++) {
            wdH[tid + j * 256] = wsH[tid + j * 256];
            wdL[tid + j * 256] = wsL[tid + j * 256];
        }
        __syncthreads();
#pragma unroll
        for (int k = 0; k < 8; k++) {
            wmma::fragment<wmma::matrix_a, 16, 16, 16, __nv_bfloat16, wmma::row_major> a0, a1;
            wmma::fragment<wmma::matrix_b, 16, 16, 16, __nv_bfloat16, wmma::row_major> bf[4];
            wmma::load_matrix_sync(a0, Ah + m0 * 128 + k * 16, 128);
            wmma::load_matrix_sync(a1, Ah + (m0 + 16) * 128 + k * 16, 128);
#pragma unroll
            for (int j = 0; j < 4; j++) wmma::load_matrix_sync(bf[j], Wh + k * 16 * 128 + n0 + 16 * j, 128);
#pragma unroll
            for (int j = 0; j < 4; j++) {
                wmma::mma_sync(accH[0][j], a0, bf[j], accH[0][j]);
                wmma::mma_sync(accH[1][j], a1, bf[j], accH[1][j]);
            }
            wmma::load_matrix_sync(a0, Al + m0 * 128 + k * 16, 128);
            wmma::load_matrix_sync(a1, Al + (m0 + 16) * 128 + k * 16, 128);
#pragma unroll
            for (int j = 0; j < 4; j++) wmma::load_matrix_sync(bf[j], Wl + k * 16 * 128 + n0 + 16 * j, 128);
#pragma unroll
            for (int j = 0; j < 4; j++) {
                wmma::mma_sync(accL[0][j], a0, bf[j], accL[0][j]);
                wmma::mma_sync(accL[1][j], a1, bf[j], accL[1][j]);
            }
        }
    }

    __syncthreads();  // smem reuse: all warps done reading A/W
#pragma unroll
    for (int i = 0; i < 2; i++)
#pragma unroll
        for (int j = 0; j < 4; j++) {
            // store transposed: element (pix, oc) at O[oc*128 + pix]
            wmma::store_matrix_sync(Oh + (n0 + 16 * j) * 128 + (m0 + 16 * i), accH[i][j], 128, wmma::mem_col_major);
            wmma::store_matrix_sync(Ol + (n0 + 16 * j) * 128 + (m0 + 16 * i), accL[i][j], 128, wmma::mem_col_major);
        }
    __syncthreads();

    for (int i = tid; i < 16384; i += 256) {
        int oc = i >> 7, p2 = i & 127;
        float y = g_sh[oc] * Oh[oc * 128 + p2] + g_sl[oc] * Ol[oc * 128 + p2];
        int g2 = blockIdx.x * 128 + p2;
        int b2 = g2 / 3136;
        int r2 = g2 - b2 * 3136;
        out[((long)b2 * 128 + oc) * 3136 + r2] = y;
    }
}

// ---------------------------------------------------------------------------
extern "C" void kernel_launch(void* const* d_in, const int* in_sizes, int n_in,
                              void* d_out, int out_size) {
    const float* x   = (const float*)d_in[0];
    const float* wh  = (const float*)d_in[1];
    const float* wl  = (const float*)d_in[2];
    const float* ash = (const float*)d_in[3];
    const float* asl = (const float*)d_in[4];
    float* out = (float*)d_out;

    cudaFuncSetAttribute(conv_kernel, cudaFuncAttributeMaxDynamicSharedMemorySize, 131072);

    mask_kernel<<<25088, 256>>>(x);          // 200704 cells / 8 per block
    border_kernel<<<3648, 256>>>();          // 933888 / 256
    quant_kernel<<<1792, 256>>>(x, ash, asl);// 32*56 rows
    wq_kernel<<<128, 128>>>(wh, ash, 1);
    wq_kernel<<<128, 128>>>(wl, asl, 0);
    conv_kernel<<<784, 256, 131072>>>(out);  // 100352 / 128 pixels
}

// round 7
// speedup vs baseline: 5.3095x; 5.3095x over previous
#include <cuda_runtime.h>
#include <cuda_bf16.h>
#include <cstdint>

// ---------------------------------------------------------------------------
// tcgen05 is an arch-SPECIFIC (sm_10Xa) feature. The harness also builds a
// baseline compute_103 PTX variant which rejects tcgen05 — so the tensor-core
// kernel body must compile away there. GB300 loads the exact sm_103a cubin,
// so the guarded-out fallback never executes.
// ---------------------------------------------------------------------------
#if (defined(__CUDA_ARCH_SPECIFIC__) && (__CUDA_ARCH_SPECIFIC__ >= 1000)) || \
    defined(__CUDA_ARCH_FEAT_SM103_ALL) || defined(__CUDA_ARCH_FEAT_SM100_ALL) || \
    defined(__CUDA_ARCH_FEAT_SM101_ALL)
#define HAS_TCGEN05 1
#endif

// ---------------------------------------------------------------------------
// Problem constants
#define PAD_ELEMS (32*58*58*128)

// Device scratch (allocation-free rule: __device__ globals)
__device__ __nv_bfloat16 g_qh[PAD_ELEMS];      // padded NHWC uint8-valued acts (high)
__device__ __nv_bfloat16 g_ql[PAD_ELEMS];      // padded NHWC uint4-valued acts (low)
__device__ __nv_bfloat16 g_wqh[9 * 128 * 128]; // [tap][oc][ic]  (K-major for tcgen05 B)
__device__ __nv_bfloat16 g_wql[9 * 128 * 128];
__device__ float g_sh[128];                    // s_w_high[oc] * act_scale_high
__device__ float g_sl[128];
__device__ unsigned char g_mask[32 * 128 * 49];

// ---------------------------------------------------------------------------
// PTX helpers (inlined)
// ---------------------------------------------------------------------------
__device__ __forceinline__ uint32_t smem_u32(const void* p) {
    uint32_t a;
    asm("{ .reg .u64 t; cvta.to.shared.u64 t, %1; cvt.u32.u64 %0, t; }" : "=r"(a) : "l"(p));
    return a;
}

#ifdef HAS_TCGEN05
__device__ __forceinline__ uint32_t elect_one_pred() {
    uint32_t pred;
    asm volatile("{\n\t.reg .pred p;\n\telect.sync _|p, 0xFFFFFFFF;\n\tselp.b32 %0, 1, 0, p;\n\t}" : "=r"(pred));
    return pred;
}
#define MBARRIER_INIT(addr, cnt) \
    asm volatile("mbarrier.init.shared.b64 [%0], %1;" :: "r"(addr), "r"(cnt) : "memory")
#define MBARRIER_WAIT_PARITY(addr, par) do { \
    uint32_t _m = (addr), _p = (par), _d; \
    asm volatile("{\n\t.reg .pred p;\n\tmbarrier.try_wait.parity.acquire.cta.shared::cta.b64 p, [%1], %2;\n\tselp.b32 %0, 1, 0, p;\n\t}" \
        : "=r"(_d) : "r"(_m), "r"(_p) : "memory"); \
    if (!_d) { \
        asm volatile("{\n\t.reg .pred P1;\n\tWL%=:\n\tmbarrier.try_wait.parity.acquire.cta.shared::cta.b64 P1, [%0], %1, 0x989680;\n\t@P1 bra.uni WD%=;\n\tbra.uni WL%=;\n\tWD%=:\n\t}" \
            :: "r"(_m), "r"(_p) : "memory"); \
    } \
} while (0)
#define TCGEN05_ALLOC(saddr, ncols) \
    asm volatile("tcgen05.alloc.cta_group::1.sync.aligned.shared::cta.b32 [%0], %1;" :: "r"(saddr), "r"(ncols) : "memory")
#define TCGEN05_DEALLOC(tm, ncols) \
    asm volatile("tcgen05.dealloc.cta_group::1.sync.aligned.b32 %0, %1;" :: "r"(tm), "r"(ncols))
#define TCGEN05_RELINQ() \
    asm volatile("tcgen05.relinquish_alloc_permit.cta_group::1.sync.aligned;")
#define TCGEN05_COMMIT(mb) \
    asm volatile("tcgen05.commit.cta_group::1.mbarrier::arrive::one.shared::cluster.b64 [%0];" :: "r"(mb) : "memory")
#define TCGEN05_FENCE_AFTER()  asm volatile("tcgen05.fence::after_thread_sync;" ::: "memory")
#define TCGEN05_FENCE_BEFORE() asm volatile("tcgen05.fence::before_thread_sync;" ::: "memory")
#define TCGEN05_WAIT_LD()      asm volatile("tcgen05.wait::ld.sync.aligned;" ::: "memory")
#define FENCE_PROXY_ASYNC()    asm volatile("fence.proxy.async.shared::cta;" ::: "memory")

#define TCGEN05_LD_32X32B_X32(r, a) \
    asm volatile( \
        "tcgen05.ld.sync.aligned.32x32b.x32.b32 " \
        "{%0, %1, %2, %3, %4, %5, %6, %7, %8, %9, %10, %11, %12, %13, %14, %15, " \
        " %16, %17, %18, %19, %20, %21, %22, %23, %24, %25, %26, %27, %28, %29, %30, %31}, [%32];" \
        : "=r"((r)[0]),  "=r"((r)[1]),  "=r"((r)[2]),  "=r"((r)[3]), \
          "=r"((r)[4]),  "=r"((r)[5]),  "=r"((r)[6]),  "=r"((r)[7]), \
          "=r"((r)[8]),  "=r"((r)[9]),  "=r"((r)[10]), "=r"((r)[11]), \
          "=r"((r)[12]), "=r"((r)[13]), "=r"((r)[14]), "=r"((r)[15]), \
          "=r"((r)[16]), "=r"((r)[17]), "=r"((r)[18]), "=r"((r)[19]), \
          "=r"((r)[20]), "=r"((r)[21]), "=r"((r)[22]), "=r"((r)[23]), \
          "=r"((r)[24]), "=r"((r)[25]), "=r"((r)[26]), "=r"((r)[27]), \
          "=r"((r)[28]), "=r"((r)[29]), "=r"((r)[30]), "=r"((r)[31]) \
        : "r"(a))

// bf16 SS MMA, cta_group::1, fp32 accum
__device__ __forceinline__ void mma_f16_ss(uint32_t d, uint64_t ad, uint64_t bd,
                                           uint32_t idesc, uint32_t en) {
    asm volatile(
        "{\n\t.reg .pred p;\n\tsetp.ne.u32 p, %4, 0;\n\t"
        "tcgen05.mma.cta_group::1.kind::f16 [%0], %1, %2, %3, {%5, %5, %5, %5}, p;\n\t}"
        :: "r"(d), "l"(ad), "l"(bd), "r"(idesc), "r"(en), "r"(0u)
        : "memory");
}
#endif // HAS_TCGEN05

// idesc: dtype=F32, atype=btype=BF16, N=128, M=128, K-major both
#define MMA_IDESC 0x8200490u
// SW128 desc base: layout=2 (SW128), version=1, SBO=64 (1024B per 8-row group), LBO=1
#define DESC_BASE_SW128 ((2ull << 61) | (1ull << 46) | (64ull << 32) | (1ull << 16))

// ---------------------------------------------------------------------------
// 1) Pool mask
// ---------------------------------------------------------------------------
__global__ void mask_kernel(const float* __restrict__ x) {
    int cell = blockIdx.x * 8 + (threadIdx.x >> 5);
    int lane = threadIdx.x & 31;
    int b   = cell / (128 * 49);
    int rem = cell - b * (128 * 49);
    int c   = rem / 49;
    int pc  = rem - c * 49;
    int bh  = pc / 7;
    int bw  = pc - bh * 7;
    const float* base = x + (((b * 128 + c) * 56 + bh * 8) * 56 + bw * 8);
    int r = lane >> 3, col = lane & 7;
    float s = base[r * 56 + col] + base[(r + 4) * 56 + col];
#pragma unroll
    for (int o = 16; o > 0; o >>= 1) s += __shfl_xor_sync(0xffffffffu, s, o);
    if (lane == 0) g_mask[cell] = (s * (1.0f / 64.0f)) >= 0.05f ? 1 : 0;
}

// ---------------------------------------------------------------------------
// 2) Zero padded borders
// ---------------------------------------------------------------------------
__global__ void border_kernel() {
    int idx = blockIdx.x * 256 + threadIdx.x;   // < 933888
    int c = idx & 127;
    int t = idx >> 7;
    int b = t / 228;
    int e = t - b * 228;
    int h, w;
    if (e < 58)       { h = 0;  w = e; }
    else if (e < 116) { h = 57; w = e - 58; }
    else { int r = e - 116; h = 1 + (r >> 1); w = (r & 1) ? 57 : 0; }
    long off = (((long)(b * 58 + h)) * 58 + w) * 128 + c;
    __nv_bfloat16 z = __float2bfloat16(0.0f);
    g_qh[off] = z;
    g_ql[off] = z;
}

// ---------------------------------------------------------------------------
// 3) Quantize acts, NCHW -> padded NHWC bf16
// ---------------------------------------------------------------------------
__global__ void quant_kernel(const float* __restrict__ x,
                             const float* __restrict__ p_sh,
                             const float* __restrict__ p_sl) {
    __shared__ float xs[128 * 57];
    __shared__ unsigned char ms[128 * 7];
    int blk = blockIdx.x;
    int b = blk / 56, h = blk - b * 56;
    int tid = threadIdx.x;
    for (int i = tid; i < 128 * 56; i += 256) {
        int c = i / 56, w = i - c * 56;
        xs[c * 57 + w] = x[(((b * 128 + c) * 56 + h)) * 56 + w];
    }
    for (int i = tid; i < 128 * 7; i += 256) {
        int c = i / 7, bw = i - c * 7;
        ms[i] = g_mask[(b * 128 + c) * 49 + (h >> 3) * 7 + bw];
    }
    __syncthreads();
    float sh = *p_sh, sl = *p_sl;
    long pixrow = (((long)(b * 58) + h + 1) * 58 + 1) * 128;
    unsigned int* outh = (unsigned int*)g_qh;
    unsigned int* outl = (unsigned int*)g_ql;
    for (int i = tid; i < 64 * 56; i += 256) {
        int w  = i >> 6;
        int c2 = i & 63;
        int c  = c2 * 2;
        int mb = w >> 3;
        bool m0 = ms[c * 7 + mb] != 0;
        bool m1 = ms[(c + 1) * 7 + mb] != 0;
        float v0 = xs[c * 57 + w], v1 = xs[(c + 1) * 57 + w];
        float q0h = m0 ? fminf(fmaxf(rintf(v0 / sh), 0.f), 255.f) : 0.f;
        float q1h = m1 ? fminf(fmaxf(rintf(v1 / sh), 0.f), 255.f) : 0.f;
        float q0l = m0 ? 0.f : fminf(fmaxf(rintf(v0 / sl), 0.f), 15.f);
        float q1l = m1 ? 0.f : fminf(fmaxf(rintf(v1 / sl), 0.f), 15.f);
        unsigned uh = (unsigned)__bfloat16_as_ushort(__float2bfloat16(q0h)) |
                      ((unsigned)__bfloat16_as_ushort(__float2bfloat16(q1h)) << 16);
        unsigned ul = (unsigned)__bfloat16_as_ushort(__float2bfloat16(q0l)) |
                      ((unsigned)__bfloat16_as_ushort(__float2bfloat16(q1l)) << 16);
        long widx = (pixrow + (long)w * 128 + c) >> 1;
        outh[widx] = uh;
        outl[widx] = ul;
    }
}

// ---------------------------------------------------------------------------
// 4) Weight quantization -> [tap][oc][ic]  (K-major B for tcgen05)
// ---------------------------------------------------------------------------
__global__ void wq_kernel(const float* __restrict__ w, const float* __restrict__ ascale, int high) {
    __shared__ float red[128];
    int oc = blockIdx.x;
    int ic = threadIdx.x;
    float n = high ? 127.0f : 7.0f;
    const float* wp = w + ((long)oc * 128 + ic) * 9;
    float m = 0.f;
#pragma unroll
    for (int t = 0; t < 9; t++) m = fmaxf(m, fabsf(wp[t]));
    red[ic] = m;
    __syncthreads();
    for (int s = 64; s > 0; s >>= 1) {
        if (ic < s) red[ic] = fmaxf(red[ic], red[ic + s]);
        __syncthreads();
    }
    float s_w = red[0] / n;
    __nv_bfloat16* dst = high ? g_wqh : g_wql;
#pragma unroll
    for (int t = 0; t < 9; t++) {
        float q = fminf(fmaxf(rintf(wp[t] / s_w), -n), n);
        dst[t * 16384 + oc * 128 + ic] = __float2bfloat16(q);
    }
    if (ic == 0) (high ? g_sh : g_sl)[oc] = s_w * (*ascale);
}

// ---------------------------------------------------------------------------
// 5) tcgen05 implicit-GEMM dual conv.
//    CTA: 128 pixels x 128 oc, TMEM accumulators Dh (cols 0..127) + Dl (128..255).
//    18 stages (9 taps x {H,L}), each stage = A tile (32KB) + B tile (32KB) in a
//    3-deep SMEM ring; buffer reuse gated by tcgen05.commit -> mbarrier.
//    SMEM tiles: 128x128 bf16, SW128 blocked-atom layout (8 rows x 64 bf16 atoms,
//    atom_offset = (row>>3) + (col>>6)*16).
// ---------------------------------------------------------------------------
__global__ void __launch_bounds__(256, 1) conv_kernel(float* __restrict__ out) {
#ifdef HAS_TCGEN05
    extern __shared__ __align__(16) char dsm[];
    __shared__ uint32_t s_tmem;
    __shared__ __align__(8) uint64_t s_bar[3];

    int tid = threadIdx.x;
    int wid = tid >> 5;
    int lane = tid & 31;

    uint32_t base = (smem_u32(dsm) + 1023u) & ~1023u;

    if (tid == 0) {
#pragma unroll
        for (int i = 0; i < 3; i++) MBARRIER_INIT(smem_u32(&s_bar[i]), 1);
    }
    if (wid == 0) TCGEN05_ALLOC(smem_u32(&s_tmem), 256);
    __syncthreads();
    uint32_t tmem = s_tmem;

    // Per-thread fixed copy geometry: 8 rows each, 1 x 16B chunk per row.
    int col16 = tid & 15;
    long rbase[8];
    uint32_t dst16[8];
#pragma unroll
    for (int j = 0; j < 8; j++) {
        int row = (tid >> 4) + 16 * j;
        int g = blockIdx.x * 128 + row;
        int b = g / 3136;
        int r = g - b * 3136;
        int h = r / 56;
        int w = r - h * 56;
        rbase[j] = (((long)(b * 58 + h)) * 58 + w) * 128;
        uint32_t off = ((uint32_t)(row >> 3) + (uint32_t)(col16 >> 3) * 16u) * 1024u
                       + (uint32_t)(row & 7) * 128u + (uint32_t)(col16 & 7) * 16u;
        dst16[j] = off ^ ((off >> 3) & 0x70u);
    }

    const int koff[8] = {0, 2, 4, 6, 1024, 1026, 1028, 1030};

#pragma unroll 1
    for (int s = 0; s < 18; s++) {
        int tap = s >> 1;
        int isH = !(s & 1);
        int buf = s % 3;
        uint32_t bufA = base + (uint32_t)buf * 65536u;
        uint32_t bufB = bufA + 32768u;

        if (s >= 3) {
            MBARRIER_WAIT_PARITY(smem_u32(&s_bar[buf]), ((s / 3) - 1) & 1);
        }

        const __nv_bfloat16* Asrc = isH ? g_qh : g_ql;
        const __nv_bfloat16* Bsrc = isH ? g_wqh : g_wql;
        int kh = tap / 3, kw = tap - kh * 3;
        long tapoff = (long)(kh * 58 + kw) * 128;
        const uint4* bsrc4 = (const uint4*)(Bsrc + tap * 16384);

#pragma unroll
        for (int j = 0; j < 8; j++) {
            uint4 va = *((const uint4*)(Asrc + rbase[j] + tapoff) + col16);
            asm volatile("st.shared.v4.b32 [%0], {%1,%2,%3,%4};"
                :: "r"(bufA + dst16[j]), "r"(va.x), "r"(va.y), "r"(va.z), "r"(va.w));
            uint4 vb = bsrc4[((tid >> 4) + 16 * j) * 16 + col16];
            asm volatile("st.shared.v4.b32 [%0], {%1,%2,%3,%4};"
                :: "r"(bufB + dst16[j]), "r"(vb.x), "r"(vb.y), "r"(vb.z), "r"(vb.w));
        }
        FENCE_PROXY_ASYNC();
        __syncthreads();

        if (wid == 0 && elect_one_pred()) {
            TCGEN05_FENCE_AFTER();
            uint64_t ad = DESC_BASE_SW128 | ((uint64_t)(bufA >> 4) & 0x3FFF);
            uint64_t bd = DESC_BASE_SW128 | ((uint64_t)(bufB >> 4) & 0x3FFF);
            uint32_t dcol = tmem + (isH ? 0u : 128u);
#pragma unroll
            for (int k = 0; k < 8; k++) {
                mma_f16_ss(dcol, ad + koff[k], bd + koff[k], MMA_IDESC,
                           (tap > 0) || (k > 0));
            }
            TCGEN05_COMMIT(smem_u32(&s_bar[buf]));
        }
    }

    // Drain the last three stage commits (6th commit per buffer -> parity 1).
#pragma unroll
    for (int b2 = 0; b2 < 3; b2++) {
        MBARRIER_WAIT_PARITY(smem_u32(&s_bar[b2]), 1);
    }
    TCGEN05_FENCE_AFTER();

    // Epilogue: warps 0-3 cover oc 0..63, warps 4-7 cover oc 64..127.
    int p = (wid & 3) * 32 + lane;
    int g = blockIdx.x * 128 + p;
    int bb = g / 3136;
    int rr = g - bb * 3136;
    float* obase = out + ((long)bb * 128) * 3136 + rr;
    int cb0 = (wid >> 2) * 64;
#pragma unroll
    for (int halfc = 0; halfc < 2; halfc++) {
        int cb = cb0 + 32 * halfc;
        uint32_t rh[32], rl[32];
        TCGEN05_LD_32X32B_X32(rh, tmem + cb);
        TCGEN05_LD_32X32B_X32(rl, tmem + 128 + cb);
        TCGEN05_WAIT_LD();
#pragma unroll
        for (int j = 0; j < 32; j++) {
            int oc = cb + j;
            float y = g_sh[oc] * __uint_as_float(rh[j]) + g_sl[oc] * __uint_as_float(rl[j]);
            obase[(long)oc * 3136] = y;
        }
    }
    TCGEN05_FENCE_BEFORE();
    __syncthreads();
    if (wid == 0) {
        TCGEN05_RELINQ();
        TCGEN05_DEALLOC(tmem, 256);
    }
#endif // HAS_TCGEN05
}

// ---------------------------------------------------------------------------
extern "C" void kernel_launch(void* const* d_in, const int* in_sizes, int n_in,
                              void* d_out, int out_size) {
    const float* x   = (const float*)d_in[0];
    const float* wh  = (const float*)d_in[1];
    const float* wl  = (const float*)d_in[2];
    const float* ash = (const float*)d_in[3];
    const float* asl = (const float*)d_in[4];
    float* out = (float*)d_out;

    cudaFuncSetAttribute(conv_kernel, cudaFuncAttributeMaxDynamicSharedMemorySize, 197632);

    mask_kernel<<<25088, 256>>>(x);
    border_kernel<<<3648, 256>>>();
    quant_kernel<<<1792, 256>>>(x, ash, asl);
    wq_kernel<<<128, 128>>>(wh, ash, 1);
    wq_kernel<<<128, 128>>>(wl, asl, 0);
    conv_kernel<<<784, 256, 197632>>>(out);
}